// round 3
// baseline (speedup 1.0000x reference)
#include <cuda_runtime.h>

// InfoEnlargeEmbedding: out[b,l,:] = concat(x[b,l,:], x[b,idxs[b,0],:], x[b,idxs[b,1],:])
// B=64, L=1024, D=256, K=2.
// R3: balanced warps. 256 threads, 16 rows/block. Every thread: 4 DRAM copy
// loads + 1 L2-hit gather load + 12 streaming stores. No smem, no syncs.

static constexpr int B = 64;
static constexpr int L = 1024;
static constexpr int D4 = 64;               // float4 per source row
static constexpr int K = 2;
static constexpr int OUT4 = D4 * (1 + K);   // 192 float4 per output row
static constexpr int R = 16;                // rows per block
static constexpr int T = 256;               // threads per block
static constexpr int CPT = (R * D4) / T;    // 4 copy float4 per thread
static constexpr int GRT = R / 2;           // 8 gather-store rows per thread

__global__ void __launch_bounds__(T)
info_enlarge_kernel(const float4* __restrict__ x,
                    const int* __restrict__ idxs,
                    float4* __restrict__ out) {
    const int row0 = blockIdx.x * R;        // base bl; R divides L so same b
    const int b    = row0 >> 10;            // / L
    const int t    = threadIdx.x;

    // ---- gather value: one L2-hit load per thread (2 threads per column) ----
    const int g  = t & 127;                 // gather column 0..127
    const int h  = t >> 7;                  // which half of the 16 rows
    const int k  = g >> 6;
    const int dd = g & (D4 - 1);
    const int li = __ldg(idxs + b * K + k);
    const float4 gv = __ldg(x + ((size_t)b * L + li) * D4 + dd);

    // ---- copy region: 4 independent DRAM loads per thread ----
    float4 cv[CPT];
    #pragma unroll
    for (int u = 0; u < CPT; u++) {
        const int idx = t + u * T;          // 0..1023
        const int r = idx >> 6, c = idx & (D4 - 1);
        cv[u] = __ldcs(x + (size_t)(row0 + r) * D4 + c);
    }

    // ---- copy stores ----
    #pragma unroll
    for (int u = 0; u < CPT; u++) {
        const int idx = t + u * T;
        const int r = idx >> 6, c = idx & (D4 - 1);
        __stcs(out + (size_t)(row0 + r) * OUT4 + c, cv[u]);
    }

    // ---- gather broadcast stores: 8 rows per thread ----
    const int rbase = row0 + h * GRT;
    #pragma unroll
    for (int j = 0; j < GRT; j++)
        __stcs(out + (size_t)(rbase + j) * OUT4 + D4 + g, gv);
}

extern "C" void kernel_launch(void* const* d_in, const int* in_sizes, int n_in,
                              void* d_out, int out_size) {
    const float4* x  = (const float4*)d_in[0];
    const int* idxs  = (const int*)d_in[1];
    float4* out      = (float4*)d_out;

    info_enlarge_kernel<<<(B * L) / R, T>>>(x, idxs, out);
}

// round 4
// speedup vs baseline: 1.0365x; 1.0365x over previous
#include <cuda_runtime.h>
#include <cstdint>

// InfoEnlargeEmbedding: out[b,l,:] = concat(x[b,l,:], x[b,idxs[b,0],:], x[b,idxs[b,1],:])
// B=64, L=1024, D=256, K=2.
// R4: assemble 16-row (48 KiB) output tiles in SMEM, drain via one
// cp.async.bulk store per block. Reads default-cached (x stays L2-resident).

static constexpr int B = 64;
static constexpr int L = 1024;
static constexpr int D4 = 64;               // float4 per source row
static constexpr int K = 2;
static constexpr int OUT4 = D4 * (1 + K);   // 192 float4 per output row
static constexpr int R = 16;                // rows per block tile
static constexpr int T = 256;               // threads per block
static constexpr int CPT = (R * D4) / T;    // 4 copy float4 per thread
static constexpr int GRT = R / 2;           // 8 gather rows per thread
static constexpr int TILE_BYTES = R * OUT4 * 16;  // 49152

__device__ __forceinline__ uint32_t smem_u32(const void* p) {
    uint32_t a;
    asm("{ .reg .u64 t; cvta.to.shared.u64 t, %1; cvt.u32.u64 %0, t; }"
        : "=r"(a) : "l"(p));
    return a;
}

__global__ void __launch_bounds__(T)
info_enlarge_kernel(const float4* __restrict__ x,
                    const int* __restrict__ idxs,
                    float4* __restrict__ out) {
    __shared__ float4 tile[R * OUT4];       // 48 KiB, output-layout tile

    const int row0 = blockIdx.x * R;        // base bl; R divides L so same b
    const int b    = row0 >> 10;            // / L
    const int t    = threadIdx.x;

    // ---- gather value: one L2-hit load per thread (2 threads per column) ----
    const int g  = t & 127;                 // gather column 0..127
    const int h  = t >> 7;                  // row half
    const int k  = g >> 6;
    const int dd = g & (D4 - 1);
    const int li = __ldg(idxs + b * K + k);
    const float4 gv = __ldg(x + ((size_t)b * L + li) * D4 + dd);

    // ---- copy region: 4 independent loads (mostly L2 hits), keep x cached ----
    float4 cv[CPT];
    #pragma unroll
    for (int u = 0; u < CPT; u++) {
        const int idx = t + u * T;          // 0..1023
        const int r = idx >> 6, c = idx & (D4 - 1);
        cv[u] = x[(size_t)(row0 + r) * D4 + c];
    }

    // ---- assemble tile in SMEM ----
    #pragma unroll
    for (int u = 0; u < CPT; u++) {
        const int idx = t + u * T;
        const int r = idx >> 6, c = idx & (D4 - 1);
        tile[r * OUT4 + c] = cv[u];
    }
    const int rbase = h * GRT;
    #pragma unroll
    for (int j = 0; j < GRT; j++)
        tile[(rbase + j) * OUT4 + D4 + g] = gv;

    __syncthreads();

    // ---- single bulk-async store of the whole 48 KiB tile ----
    if (t == 0) {
        asm volatile("fence.proxy.async.shared::cta;" ::: "memory");
        const uint32_t saddr = smem_u32(tile);
        void* gptr = (void*)(out + (size_t)row0 * OUT4);
        asm volatile(
            "cp.async.bulk.global.shared::cta.bulk_group [%0], [%1], %2;"
            :: "l"(gptr), "r"(saddr), "n"(TILE_BYTES)
            : "memory");
        asm volatile("cp.async.bulk.commit_group;" ::: "memory");
        asm volatile("cp.async.bulk.wait_group 0;" ::: "memory");
    }
}

extern "C" void kernel_launch(void* const* d_in, const int* in_sizes, int n_in,
                              void* d_out, int out_size) {
    const float4* x  = (const float4*)d_in[0];
    const int* idxs  = (const int*)d_in[1];
    float4* out      = (float4*)d_out;

    info_enlarge_kernel<<<(B * L) / R, T>>>(x, idxs, out);
}